// round 1
// baseline (speedup 1.0000x reference)
#include <cuda_runtime.h>
#include <math.h>

// Problem shape (fixed by the dataset)
#define B_ 8
#define T_ 2048
#define V_ 10
#define H_ 5
#define NC 32   // max candidates per (h,t); overflow -> full-scan fallback

// Scratch tables (no allocations allowed -> __device__ globals)
__device__ int g_cand[H_ * T_ * NC];  // candidate s, stored in DESCENDING s order
__device__ int g_cnt [H_ * T_];

// ---------------------------------------------------------------------------
// Kernel 1: per (h,t) enumerate lattice points s ~= t - off - 2*pi*k and keep
// every s whose angular distance delta could possibly win the float32 argmax
// (margin covers the x0 digit spread, the -10000 mask shift, and ulp slop).
// One warp per (h,t); deterministic, ordered compaction via ballot.
// ---------------------------------------------------------------------------
__global__ void k_cand(const float* __restrict__ offs,
                       const float* __restrict__ p_eps,
                       const float* __restrict__ p_C)
{
    int w    = (blockIdx.x * blockDim.x + threadIdx.x) >> 5;
    int lane = threadIdx.x & 31;
    if (w >= H_ * T_) return;
    int h = w / T_;
    int t = w - h * T_;

    const double TWO_PI = 6.283185307179586;
    double off  = (double)offs[h];
    double quad = 0.5 * (double)p_eps[0];
    double C    = (double)p_C[0];
    // relative score margin: x0 spread (quad*81/C ~ 2.03e-5) * 3 safety + slop
    double m = 3.0 * (quad * 81.0 / C) + 1e-6;

    double a = (double)t - off;
    int kmin = (int)floor((a - 2047.5) / TWO_PI) - 1;
    int kmax = (int)ceil ((a + 0.5)    / TWO_PI) + 1;

    // pass 1: min delta^2 over valid s in [0, 2047]
    double best = 1e30;
    for (int k = kmin + lane; k <= kmax; k += 32) {
        double r = a - TWO_PI * (double)k;
        double s = rint(r);
        if (s >= 0.0 && s <= 2047.0) {
            double d = r - s;
            double d2 = d * d;
            if (d2 < best) best = d2;
        }
    }
#pragma unroll
    for (int o = 16; o; o >>= 1) {
        double v = __shfl_xor_sync(0xffffffffu, best, o);
        if (v < best) best = v;
    }
    // window: cos(d) >= cos(dmin)*(1-m)  ->  d^2 <= dmin^2 + 2m (small-angle)
    double W2 = best + 2.0 * m + 1e-9;

    // pass 2: ordered compaction (k ascending -> s descending), deterministic
    int base = 0;
    for (int k0 = kmin; k0 <= kmax; k0 += 32) {
        int k = k0 + lane;
        bool qual = false; int sv = 0;
        if (k <= kmax) {
            double r = a - TWO_PI * (double)k;
            double s = rint(r);
            if (s >= 0.0 && s <= 2047.0) {
                double d = r - s;
                if (d * d <= W2) { qual = true; sv = (int)s; }
            }
        }
        unsigned mask = __ballot_sync(0xffffffffu, qual);
        if (qual) {
            int pos = base + __popc(mask & ((1u << lane) - 1u));
            if (pos < NC) g_cand[(h * T_ + t) * NC + pos] = sv;
        }
        base += __popc(mask);
    }
    if (lane == 0) g_cnt[h * T_ + t] = base;
}

// ---------------------------------------------------------------------------
// Kernel 2: one thread per (b,t). Faithful float32 reproduction of the
// reference pipeline, but scores are evaluated only at the candidates.
// exp(score-max) is exactly {0,1} at this score magnitude, so softmax is
// uniform over the bitwise-argmax tie set.
// ---------------------------------------------------------------------------
__global__ void k_main(const int*   __restrict__ ids,
                       const float* __restrict__ o_w,
                       const float* __restrict__ w1_abc,
                       const float* __restrict__ w2_s,
                       const float* __restrict__ p_C,
                       const float* __restrict__ p_eps,
                       const float* __restrict__ p_qk,
                       const float* __restrict__ offs,
                       float*       __restrict__ out)
{
    int idx = blockIdx.x * blockDim.x + threadIdx.x;
    if (idx >= B_ * T_) return;
    int b = idx / T_;
    int t = idx - b * T_;
    const int* idb = ids + b * T_;

    const float C   = p_C[0];
    const float eps = p_eps[0];
    const float qk  = p_qk[0];
    const float quad = __fdiv_rn(eps, 2.0f);               // exact (/2)
    const float SQ2  = 1.41421356237309514547f;            // fl32(sqrt(2))

    int   dt_i = idb[t];
    float dt   = (float)dt_i;
    float x0t  = __fsub_rn(C, __fmul_rn(quad, __fmul_rn(dt, dt)));
    float tf   = (float)t;
    float ct   = cosf(tf);
    float st   = sinf(tf);

    float A[H_];

    for (int h = 0; h < H_; ++h) {
        float off = offs[h];
        float co = cosf(off), so = sinf(off);
        float qb0 = __fmul_rn(co, qk);
        float qb1 = __fmul_rn(-so, qk);
        float q0  = __fmul_rn(x0t, qb0);
        float q1  = __fmul_rn(x0t, qb1);
        float qr0 = __fsub_rn(__fmul_rn(q0, ct), __fmul_rn(q1, st));
        float qr1 = __fadd_rn(__fmul_rn(q0, st), __fmul_rn(q1, ct));

        int cnt = g_cnt[h * T_ + t];

        if (cnt > 0 && cnt <= NC) {
            const int* cp = g_cand + (h * T_ + t) * NC;
            float scv[NC];
            float dsv[NC];
            float mx = -3.402823466e38f;
            // iterate in ASCENDING s (stored descending) to mirror the
            // reference's s-ordered accumulation
            for (int i = 0; i < cnt; ++i) {
                int   s   = cp[cnt - 1 - i];
                float ds  = (float)idb[s];
                float x0s = __fsub_rn(C, __fmul_rn(quad, __fmul_rn(ds, ds)));
                float kp  = __fmul_rn(x0s, qk);
                float sf  = (float)s;
                float cs  = cosf(sf), ss = sinf(sf);
                float kr0 = __fmul_rn(kp, cs);
                float kr1 = __fmul_rn(kp, ss);
                float num = __fmaf_rn(qr1, kr1, __fmul_rn(qr0, kr0)); // fma K-chain
                float sc  = __fdiv_rn(num, SQ2);
                if (s > t) sc = __fadd_rn(sc, -10000.0f);             // "mask"
                scv[i] = sc;
                dsv[i] = ds;
                if (sc > mx) mx = sc;
            }
            int n = 0;
            for (int i = 0; i < cnt; ++i) if (scv[i] == mx) n++;
            float wgt = __fdiv_rn(1.0f, (float)n);
            float acc = 0.0f;
            for (int i = 0; i < cnt; ++i)
                if (scv[i] == mx) acc = __fmaf_rn(wgt, dsv[i], acc);
            A[h] = acc;
        } else {
            // bulletproof fallback: full scan over all s
            float mx = -3.402823466e38f;
            int   n = 0;
            int   sumd = 0;
            for (int s = 0; s < T_; ++s) {
                float ds  = (float)idb[s];
                float x0s = __fsub_rn(C, __fmul_rn(quad, __fmul_rn(ds, ds)));
                float kp  = __fmul_rn(x0s, qk);
                float sf  = (float)s;
                float cs  = cosf(sf), ss = sinf(sf);
                float kr0 = __fmul_rn(kp, cs);
                float kr1 = __fmul_rn(kp, ss);
                float num = __fmaf_rn(qr1, kr1, __fmul_rn(qr0, kr0));
                float sc  = __fdiv_rn(num, SQ2);
                if (s > t) sc = __fadd_rn(sc, -10000.0f);
                if (sc > mx) { mx = sc; n = 1; sumd = idb[s]; }
                else if (sc == mx) { n++; sumd += idb[s]; }
            }
            A[h] = __fmul_rn(__fdiv_rn(1.0f, (float)n), (float)sumd);
        }
    }

    // ---- epilogue: output projection + MLP + decode, faithful fp32 ----
    float A0 = A[0], A1 = A[1], A2 = A[2], A3 = A[3], A4 = A[4];
    float u0 = __fadd_rn(__fadd_rn(__fmul_rn(o_w[0], A0),
                                   __fmul_rn(o_w[1], A1)),
                         __fmul_rn(o_w[2], A2));
    float u1 = __fadd_rn(__fadd_rn(__fmul_rn(o_w[3], A0),
                                   __fmul_rn(o_w[4], A3)),
                         __fmul_rn(o_w[5], A4));
    float X0 = __fadd_rn(x0t, u0);
    float X1 = __fadd_rn(dt,  u1);

    float wa = w1_abc[0], wb = w1_abc[1], wc = w1_abc[2];
    float b10 = __fsub_rn(C, 8.0f);
    float b11 = __fsub_rn(C, 9.0f);
    float twoC = __fmul_rn(2.0f, C);
    float b12 = __fsub_rn(twoC, 188.0f);
    float b13 = __fsub_rn(twoC, 189.0f);

    float p01 = __fmaf_rn(X1, 0.0f, __fmul_rn(X0, wa));  // rows 0,1: [a, 0]
    float p23 = __fmaf_rn(X1, wc,   __fmul_rn(X0, wb));  // rows 2,3: [b, c]
    float h0 = fmaxf(__fadd_rn(p01, b10), 0.0f);
    float h1 = fmaxf(__fadd_rn(p01, b11), 0.0f);
    float h2 = fmaxf(__fadd_rn(p23, b12), 0.0f);
    float h3 = fmaxf(__fadd_rn(p23, b13), 0.0f);

    float s1 = w2_s[0], s10 = w2_s[1];
    float hw = __fmul_rn(h0, s1);
    hw = __fmaf_rn(h1, -s1,  hw);
    hw = __fmaf_rn(h2, -s10, hw);
    hw = __fmaf_rn(h3,  s10, hw);
    float X1b = __fadd_rn(X1, hw);
    float X0b = __fadd_rn(X0, 0.0f);

    float os0 = __fdiv_rn(1.0f, C);
    float y0 = __fmul_rn(X0b, os0);
    float y1 = __fmul_rn(X1b, eps);

    float* o = out + (size_t)(b * T_ + t) * V_;
#pragma unroll
    for (int j = 0; j < V_; ++j) {
        float jj = (float)(j * j);
        float e0 = __fsub_rn(C, __fmul_rn(quad, jj));
        o[j] = __fmaf_rn(y1, (float)j, __fmul_rn(y0, e0));
    }
}

// ---------------------------------------------------------------------------
// Inputs (metadata order): input_ids(int32), o_w(6), w1_abc(3), w2_s(2),
// embed_const(1), decode_eps(1), qk_scale(1), rope_offsets(5). Output: f32 BxTxV.
// ---------------------------------------------------------------------------
extern "C" void kernel_launch(void* const* d_in, const int* in_sizes, int n_in,
                              void* d_out, int out_size)
{
    const int*   ids    = (const int*)  d_in[0];
    const float* o_w    = (const float*)d_in[1];
    const float* w1_abc = (const float*)d_in[2];
    const float* w2_s   = (const float*)d_in[3];
    const float* p_C    = (const float*)d_in[4];
    const float* p_eps  = (const float*)d_in[5];
    const float* p_qk   = (const float*)d_in[6];
    const float* offs   = (const float*)d_in[7];
    float* out = (float*)d_out;

    // Kernel 1: one warp per (h,t) -> H*T warps
    {
        int warps = H_ * T_;
        int threads = 128;
        int blocks = (warps * 32 + threads - 1) / threads;
        k_cand<<<blocks, threads>>>(offs, p_eps, p_C);
    }
    // Kernel 2: one thread per (b,t)
    {
        int n = B_ * T_;
        int threads = 256;
        int blocks = (n + threads - 1) / threads;
        k_main<<<blocks, threads>>>(ids, o_w, w1_abc, w2_s,
                                    p_C, p_eps, p_qk, offs, out);
    }
}

// round 2
// speedup vs baseline: 5.4944x; 5.4944x over previous
#include <cuda_runtime.h>
#include <math.h>

// Problem shape (fixed by the dataset)
#define B_ 8
#define T_ 2048
#define V_ 10
#define H_ 5
#define NC 32   // max candidates per (h,t); overflow -> full-scan fallback

// Scratch (no allocations allowed -> __device__ globals)
__device__ int   g_cand[H_ * T_ * NC];   // candidate s, DESCENDING s order
__device__ int   g_cnt [H_ * T_];
__device__ float g_cos [T_];             // cosf((float)s)
__device__ float g_sin [T_];
__device__ float g_k0  [B_ * T_];        // rotated K row, component 0 (faithful fp32)
__device__ float g_k1  [B_ * T_];        // rotated K row, component 1

// ---------------------------------------------------------------------------
// Fused prep kernel.
//   Blocks [0, CAND_BLOCKS): one warp per (h,t) — pure-fp32 lattice candidate
//     search. Exactness: off is a small exact integer, so a = t - off is an
//     exact fp32 integer. 2pi = P1 + P2 with P1 = 6.28125 (9 bits): k*P1 and
//     (a - k*P1 - s) are exact (multiples of 1/32 below 2^18). Residual
//     d = (r-s) - k*P2 is accurate to ~1e-8 — far inside the tie margin.
//   Blocks [CAND_BLOCKS, ...): one thread per (b,s) builds the faithful-fp32
//     rotated K table (bitwise identical op sequence to the reference path),
//     plus cos/sin tables for the Q side.
// ---------------------------------------------------------------------------
#define CAND_BLOCKS ((H_ * T_) / 8)          // 8 warps / 256-thr block = 1280
#define TAB_BLOCKS  ((B_ * T_) / 256)        // 64

__global__ void k_prep(const int*   __restrict__ ids,
                       const float* __restrict__ offs,
                       const float* __restrict__ p_eps,
                       const float* __restrict__ p_C,
                       const float* __restrict__ p_qk)
{
    if (blockIdx.x < CAND_BLOCKS) {
        int w    = (blockIdx.x * blockDim.x + threadIdx.x) >> 5;
        int lane = threadIdx.x & 31;
        int h = w / T_;
        int t = w - h * T_;

        const float P1     = 6.28125f;                 // 2pi hi (exact, 9 bits)
        const float P2     = 1.9353071795864769e-3f;   // 2pi lo
        const float INV2PI = 0.15915494309189535f;

        float off  = offs[h];
        float quad = 0.5f * p_eps[0];
        float C    = p_C[0];
        // relative score margin: x0 digit spread * 3 safety + slop
        float m = 3.0f * (quad * 81.0f / C) + 1e-6f;

        float a = (float)t - off;                      // exact integer
        int kmin = (int)floorf((a - 2047.5f) * INV2PI) - 1;
        int kmax = (int)ceilf ((a + 0.5f)    * INV2PI) + 1;

        // pass 1: min d^2 over valid s in [0, 2047]
        float best = 1e30f;
        for (int k = kmin + lane; k <= kmax; k += 32) {
            float kf = (float)k;
            float r  = __fmaf_rn(-kf, P1, a);          // exact
            float rf = __fmaf_rn(-kf, P2, r);
            float s  = rintf(rf);
            if (s >= 0.0f && s <= 2047.0f) {
                float d  = __fmaf_rn(-kf, P2, r - s);  // (r-s) exact; ~1e-8 err
                float d2 = d * d;
                best = fminf(best, d2);
            }
        }
#pragma unroll
        for (int o = 16; o; o >>= 1)
            best = fminf(best, __shfl_xor_sync(0xffffffffu, best, o));
        // window: cos(d) >= cos(dmin)*(1-m)  ->  d^2 <= dmin^2 + 2m
        float W2 = best + 2.0f * m + 1e-7f;

        // pass 2: ordered compaction (k ascending -> s descending)
        int base = 0;
        for (int k0 = kmin; k0 <= kmax; k0 += 32) {
            int k = k0 + lane;
            bool qual = false; int sv = 0;
            if (k <= kmax) {
                float kf = (float)k;
                float r  = __fmaf_rn(-kf, P1, a);
                float rf = __fmaf_rn(-kf, P2, r);
                float s  = rintf(rf);
                if (s >= 0.0f && s <= 2047.0f) {
                    float d = __fmaf_rn(-kf, P2, r - s);
                    if (d * d <= W2) { qual = true; sv = (int)s; }
                }
            }
            unsigned mask = __ballot_sync(0xffffffffu, qual);
            if (qual) {
                int pos = base + __popc(mask & ((1u << lane) - 1u));
                if (pos < NC) g_cand[(h * T_ + t) * NC + pos] = sv;
            }
            base += __popc(mask);
        }
        if (lane == 0) g_cnt[h * T_ + t] = base;
    } else {
        int j = (blockIdx.x - CAND_BLOCKS) * blockDim.x + threadIdx.x;
        if (j >= B_ * T_) return;
        int b = j / T_;
        int s = j - b * T_;

        float C    = p_C[0];
        float quad = __fdiv_rn(p_eps[0], 2.0f);
        float qk   = p_qk[0];

        float sf = (float)s;
        float cs = cosf(sf);
        float ss = sinf(sf);
        if (b == 0) { g_cos[s] = cs; g_sin[s] = ss; }

        float ds  = (float)ids[j];
        float x0s = __fsub_rn(C, __fmul_rn(quad, __fmul_rn(ds, ds)));
        float kp  = __fmul_rn(x0s, qk);
        g_k0[j] = __fmul_rn(kp, cs);     // faithful: k0' = (x0*qk)*cos - 0
        g_k1[j] = __fmul_rn(kp, ss);     //           k1' = (x0*qk)*sin + 0
    }
}

// ---------------------------------------------------------------------------
// Main kernel: one thread per (b,t). Scores evaluated only at candidates,
// reading the precomputed K table (bitwise-identical fp32 values).
// exp(score-max) is exactly {0,1} at this score magnitude -> softmax is
// uniform over the bitwise-argmax tie set.
// ---------------------------------------------------------------------------
__global__ void k_main(const int*   __restrict__ ids,
                       const float* __restrict__ o_w,
                       const float* __restrict__ w1_abc,
                       const float* __restrict__ w2_s,
                       const float* __restrict__ p_C,
                       const float* __restrict__ p_eps,
                       const float* __restrict__ p_qk,
                       const float* __restrict__ offs,
                       float*       __restrict__ out)
{
    int idx = blockIdx.x * blockDim.x + threadIdx.x;
    if (idx >= B_ * T_) return;
    int b = idx / T_;
    int t = idx - b * T_;
    const float* k0b = g_k0 + b * T_;
    const float* k1b = g_k1 + b * T_;

    const float C    = p_C[0];
    const float eps  = p_eps[0];
    const float qk   = p_qk[0];
    const float quad = __fdiv_rn(eps, 2.0f);
    const float SQ2  = 1.41421356237309514547f;  // fl32(sqrt(2))

    float dt  = (float)ids[b * T_ + t];
    float x0t = __fsub_rn(C, __fmul_rn(quad, __fmul_rn(dt, dt)));
    float ct  = g_cos[t];
    float st  = g_sin[t];

    float A[H_];

    for (int h = 0; h < H_; ++h) {
        float off = offs[h];
        float co = cosf(off), so = sinf(off);
        float qb0 = __fmul_rn(co, qk);
        float qb1 = __fmul_rn(-so, qk);
        float q0  = __fmul_rn(x0t, qb0);
        float q1  = __fmul_rn(x0t, qb1);
        float qr0 = __fsub_rn(__fmul_rn(q0, ct), __fmul_rn(q1, st));
        float qr1 = __fadd_rn(__fmul_rn(q0, st), __fmul_rn(q1, ct));

        int cnt = g_cnt[h * T_ + t];

        if (cnt > 0 && cnt <= NC) {
            const int* cp = g_cand + (h * T_ + t) * NC;
            float scv[NC];
            float dsv[NC];
            float mx = -3.402823466e38f;
            // ascending s (stored descending) to mirror reference ordering
            for (int i = 0; i < cnt; ++i) {
                int   s   = cp[cnt - 1 - i];
                float num = __fmaf_rn(qr1, k1b[s], __fmul_rn(qr0, k0b[s]));
                float sc  = __fdiv_rn(num, SQ2);
                if (s > t) sc = __fadd_rn(sc, -10000.0f);     // "mask"
                scv[i] = sc;
                dsv[i] = (float)ids[b * T_ + s];
                if (sc > mx) mx = sc;
            }
            int n = 0;
            for (int i = 0; i < cnt; ++i) if (scv[i] == mx) n++;
            float wgt = __fdiv_rn(1.0f, (float)n);
            float acc = 0.0f;
            for (int i = 0; i < cnt; ++i)
                if (scv[i] == mx) acc = __fmaf_rn(wgt, dsv[i], acc);
            A[h] = acc;
        } else {
            // bulletproof fallback: full scan over all s
            float mx = -3.402823466e38f;
            int n = 0, sumd = 0;
            for (int s = 0; s < T_; ++s) {
                float num = __fmaf_rn(qr1, k1b[s], __fmul_rn(qr0, k0b[s]));
                float sc  = __fdiv_rn(num, SQ2);
                if (s > t) sc = __fadd_rn(sc, -10000.0f);
                if (sc > mx) { mx = sc; n = 1; sumd = ids[b * T_ + s]; }
                else if (sc == mx) { n++; sumd += ids[b * T_ + s]; }
            }
            A[h] = __fmul_rn(__fdiv_rn(1.0f, (float)n), (float)sumd);
        }
    }

    // ---- epilogue: output projection + MLP + decode, faithful fp32 ----
    float A0 = A[0], A1 = A[1], A2 = A[2], A3 = A[3], A4 = A[4];
    float u0 = __fadd_rn(__fadd_rn(__fmul_rn(o_w[0], A0),
                                   __fmul_rn(o_w[1], A1)),
                         __fmul_rn(o_w[2], A2));
    float u1 = __fadd_rn(__fadd_rn(__fmul_rn(o_w[3], A0),
                                   __fmul_rn(o_w[4], A3)),
                         __fmul_rn(o_w[5], A4));
    float X0 = __fadd_rn(x0t, u0);
    float X1 = __fadd_rn(dt,  u1);

    float wa = w1_abc[0], wb = w1_abc[1], wc = w1_abc[2];
    float b10 = __fsub_rn(C, 8.0f);
    float b11 = __fsub_rn(C, 9.0f);
    float twoC = __fmul_rn(2.0f, C);
    float b12 = __fsub_rn(twoC, 188.0f);
    float b13 = __fsub_rn(twoC, 189.0f);

    float p01 = __fmaf_rn(X1, 0.0f, __fmul_rn(X0, wa));  // rows 0,1: [a, 0]
    float p23 = __fmaf_rn(X1, wc,   __fmul_rn(X0, wb));  // rows 2,3: [b, c]
    float h0 = fmaxf(__fadd_rn(p01, b10), 0.0f);
    float h1 = fmaxf(__fadd_rn(p01, b11), 0.0f);
    float h2 = fmaxf(__fadd_rn(p23, b12), 0.0f);
    float h3 = fmaxf(__fadd_rn(p23, b13), 0.0f);

    float s1 = w2_s[0], s10 = w2_s[1];
    float hw = __fmul_rn(h0, s1);
    hw = __fmaf_rn(h1, -s1,  hw);
    hw = __fmaf_rn(h2, -s10, hw);
    hw = __fmaf_rn(h3,  s10, hw);
    float X1b = __fadd_rn(X1, hw);
    float X0b = __fadd_rn(X0, 0.0f);

    float os0 = __fdiv_rn(1.0f, C);
    float y0 = __fmul_rn(X0b, os0);
    float y1 = __fmul_rn(X1b, eps);

    float* o = out + (size_t)(b * T_ + t) * V_;
#pragma unroll
    for (int j = 0; j < V_; ++j) {
        float jj = (float)(j * j);
        float e0 = __fsub_rn(C, __fmul_rn(quad, jj));
        o[j] = __fmaf_rn(y1, (float)j, __fmul_rn(y0, e0));
    }
}

// ---------------------------------------------------------------------------
// Inputs (metadata order): input_ids(int32), o_w(6), w1_abc(3), w2_s(2),
// embed_const(1), decode_eps(1), qk_scale(1), rope_offsets(5). Output: f32 BxTxV.
// ---------------------------------------------------------------------------
extern "C" void kernel_launch(void* const* d_in, const int* in_sizes, int n_in,
                              void* d_out, int out_size)
{
    const int*   ids    = (const int*)  d_in[0];
    const float* o_w    = (const float*)d_in[1];
    const float* w1_abc = (const float*)d_in[2];
    const float* w2_s   = (const float*)d_in[3];
    const float* p_C    = (const float*)d_in[4];
    const float* p_eps  = (const float*)d_in[5];
    const float* p_qk   = (const float*)d_in[6];
    const float* offs   = (const float*)d_in[7];
    float* out = (float*)d_out;

    k_prep<<<CAND_BLOCKS + TAB_BLOCKS, 256>>>(ids, offs, p_eps, p_C, p_qk);

    {
        int n = B_ * T_;
        int threads = 128;
        int blocks = (n + threads - 1) / threads;
        k_main<<<blocks, threads>>>(ids, o_w, w1_abc, w2_s,
                                    p_C, p_eps, p_qk, offs, out);
    }
}

// round 3
// speedup vs baseline: 9.1791x; 1.6706x over previous
#include <cuda_runtime.h>
#include <math.h>

// Problem shape (fixed by the dataset)
#define B_ 8
#define T_ 2048
#define V_ 10
#define H_ 5
#define NC 32     // max candidates per (h,t); overflow -> full-scan fallback
#define PAIRS 64  // (b,t) pairs per block in the fused main kernel

// Scratch (no allocations allowed -> __device__ globals)
__device__ int    g_candT[H_ * NC * T_];  // transposed: [(h*NC+slot)*T + t]
__device__ int    g_cnt  [H_ * T_];
__device__ float  g_cos  [T_];            // cosf((float)s)
__device__ float  g_sin  [T_];
__device__ float4 g_kv   [B_ * T_];       // {k0_rot, k1_rot, digit, 0} faithful fp32

// ---------------------------------------------------------------------------
// Prep kernel.
//   Blocks [0, CAND_BLOCKS): one warp per (h,t) — pure-fp32 lattice candidate
//     search (split-constant 2pi keeps the reduction exact to ~1e-8, far
//     inside the ~6e-5 tie margin). Candidates written TRANSPOSED for
//     coalesced reads in the main kernel.
//   Blocks [CAND_BLOCKS, ...): one thread per (b,s) builds the faithful-fp32
//     rotated K record {k0,k1,digit} (bitwise-identical op sequence to the
//     reference), plus cos/sin tables for the Q side.
// ---------------------------------------------------------------------------
#define CAND_BLOCKS ((H_ * T_) / 8)          // 8 warps per 256-thr block = 1280
#define TAB_BLOCKS  ((B_ * T_) / 256)        // 64

__global__ void k_prep(const int*   __restrict__ ids,
                       const float* __restrict__ offs,
                       const float* __restrict__ p_eps,
                       const float* __restrict__ p_C,
                       const float* __restrict__ p_qk)
{
    if (blockIdx.x < CAND_BLOCKS) {
        int w    = (blockIdx.x * blockDim.x + threadIdx.x) >> 5;
        int lane = threadIdx.x & 31;
        int h = w / T_;
        int t = w - h * T_;

        const float P1     = 6.28125f;                 // 2pi hi (exact, 9 bits)
        const float P2     = 1.9353071795864769e-3f;   // 2pi lo
        const float INV2PI = 0.15915494309189535f;

        float off  = offs[h];
        float quad = 0.5f * p_eps[0];
        float C    = p_C[0];
        float m = 3.0f * (quad * 81.0f / C) + 1e-6f;   // tie margin

        float a = (float)t - off;                      // exact integer
        int kmin = (int)floorf((a - 2047.5f) * INV2PI) - 1;
        int kmax = (int)ceilf ((a + 0.5f)    * INV2PI) + 1;

        // pass 1: min d^2 over valid s in [0, 2047]
        float best = 1e30f;
        for (int k = kmin + lane; k <= kmax; k += 32) {
            float kf = (float)k;
            float r  = __fmaf_rn(-kf, P1, a);          // exact
            float rf = __fmaf_rn(-kf, P2, r);
            float s  = rintf(rf);
            if (s >= 0.0f && s <= 2047.0f) {
                float d = __fmaf_rn(-kf, P2, r - s);   // (r-s) exact
                best = fminf(best, d * d);
            }
        }
#pragma unroll
        for (int o = 16; o; o >>= 1)
            best = fminf(best, __shfl_xor_sync(0xffffffffu, best, o));
        float W2 = best + 2.0f * m + 1e-7f;            // d^2 window

        // pass 2: ordered compaction (k ascending -> s descending), transposed
        int base = 0;
        for (int k0 = kmin; k0 <= kmax; k0 += 32) {
            int k = k0 + lane;
            bool qual = false; int sv = 0;
            if (k <= kmax) {
                float kf = (float)k;
                float r  = __fmaf_rn(-kf, P1, a);
                float rf = __fmaf_rn(-kf, P2, r);
                float s  = rintf(rf);
                if (s >= 0.0f && s <= 2047.0f) {
                    float d = __fmaf_rn(-kf, P2, r - s);
                    if (d * d <= W2) { qual = true; sv = (int)s; }
                }
            }
            unsigned mask = __ballot_sync(0xffffffffu, qual);
            if (qual) {
                int pos = base + __popc(mask & ((1u << lane) - 1u));
                if (pos < NC) g_candT[(h * NC + pos) * T_ + t] = sv;
            }
            base += __popc(mask);
        }
        if (lane == 0) g_cnt[h * T_ + t] = base;
    } else {
        int j = (blockIdx.x - CAND_BLOCKS) * blockDim.x + threadIdx.x;
        if (j >= B_ * T_) return;
        int b = j / T_;
        int s = j - b * T_;

        float C    = p_C[0];
        float quad = __fdiv_rn(p_eps[0], 2.0f);
        float qk   = p_qk[0];

        float sf = (float)s;
        float cs = cosf(sf);
        float ss = sinf(sf);
        if (b == 0) { g_cos[s] = cs; g_sin[s] = ss; }

        float ds  = (float)ids[j];
        float x0s = __fsub_rn(C, __fmul_rn(quad, __fmul_rn(ds, ds)));
        float kp  = __fmul_rn(x0s, qk);
        g_kv[j] = make_float4(__fmul_rn(kp, cs),   // k0' = (x0*qk)*cos - 0
                              __fmul_rn(kp, ss),   // k1' = (x0*qk)*sin + 0
                              ds, 0.0f);
    }
}

// ---------------------------------------------------------------------------
// Fused main kernel: one thread per (b,t,h). Block = PAIRS (b,t) pairs x H_
// heads = 320 threads. Per-head attention results meet in shared memory;
// the first PAIRS threads run the epilogue. Score arithmetic is op-for-op
// identical to the reference fp32 pipeline; softmax collapses to a uniform
// average over the bitwise-argmax tie set.
// ---------------------------------------------------------------------------
__global__ __launch_bounds__(H_ * PAIRS)
void k_fused(const int*   __restrict__ ids,
             const float* __restrict__ o_w,
             const float* __restrict__ w1_abc,
             const float* __restrict__ w2_s,
             const float* __restrict__ p_C,
             const float* __restrict__ p_eps,
             const float* __restrict__ p_qk,
             const float* __restrict__ offs,
             float*       __restrict__ out)
{
    __shared__ float A_s[H_][PAIRS];

    int tid  = threadIdx.x;
    int lane = tid & (PAIRS - 1);            // pair slot within block
    int h    = tid / PAIRS;                  // 0..H_-1
    int p    = blockIdx.x * PAIRS + lane;    // global (b,t) pair
    int b    = p / T_;
    int t    = p - b * T_;

    const float C    = p_C[0];
    const float eps  = p_eps[0];
    const float qk   = p_qk[0];
    const float quad = __fdiv_rn(eps, 2.0f);
    const float SQ2  = 1.41421356237309514547f;   // fl32(sqrt(2))

    float dt  = (float)ids[p];
    float x0t = __fsub_rn(C, __fmul_rn(quad, __fmul_rn(dt, dt)));

    // ---- per-(b,t,h) attention via candidate argmax ----
    {
        float ct  = g_cos[t];
        float st  = g_sin[t];
        float off = offs[h];
        float co = cosf(off), so = sinf(off);
        float qb0 = __fmul_rn(co, qk);
        float qb1 = __fmul_rn(-so, qk);
        float q0  = __fmul_rn(x0t, qb0);
        float q1  = __fmul_rn(x0t, qb1);
        float qr0 = __fsub_rn(__fmul_rn(q0, ct), __fmul_rn(q1, st));
        float qr1 = __fadd_rn(__fmul_rn(q0, st), __fmul_rn(q1, ct));

        int cnt = g_cnt[h * T_ + t];
        const float4* kvb = g_kv + b * T_;
        float A;

        if (cnt <= NC) {
            float scv[NC];
            float dsv[NC];
            float mx = -3.402823466e38f;
            // ascending s (slots stored s-descending) mirrors reference order
            for (int i = 0; i < cnt; ++i) {
                int    s  = g_candT[(h * NC + (cnt - 1 - i)) * T_ + t];
                float4 kv = kvb[s];
                float num = __fmaf_rn(qr1, kv.y, __fmul_rn(qr0, kv.x));
                float sc  = __fdiv_rn(num, SQ2);
                if (s > t) sc = __fadd_rn(sc, -10000.0f);     // "mask"
                scv[i] = sc;
                dsv[i] = kv.z;
                mx = fmaxf(mx, sc);
            }
            int n = 0;
            for (int i = 0; i < cnt; ++i) if (scv[i] == mx) n++;
            float wgt = __fdiv_rn(1.0f, (float)n);
            float acc = 0.0f;
            for (int i = 0; i < cnt; ++i)
                if (scv[i] == mx) acc = __fmaf_rn(wgt, dsv[i], acc);
            A = acc;
        } else {
            // bulletproof fallback: full scan
            float mx = -3.402823466e38f;
            int n = 0; float sumd = 0.0f;
            for (int s = 0; s < T_; ++s) {
                float4 kv = kvb[s];
                float num = __fmaf_rn(qr1, kv.y, __fmul_rn(qr0, kv.x));
                float sc  = __fdiv_rn(num, SQ2);
                if (s > t) sc = __fadd_rn(sc, -10000.0f);
                if (sc > mx) { mx = sc; n = 1; sumd = kv.z; }
                else if (sc == mx) { n++; sumd += kv.z; }
            }
            A = __fmul_rn(__fdiv_rn(1.0f, (float)n), sumd);
        }
        A_s[h][lane] = A;
    }
    __syncthreads();

    // ---- epilogue: first PAIRS threads, faithful fp32 ----
    if (tid < PAIRS) {
        float A0 = A_s[0][tid], A1 = A_s[1][tid], A2 = A_s[2][tid],
              A3 = A_s[3][tid], A4 = A_s[4][tid];

        float u0 = __fadd_rn(__fadd_rn(__fmul_rn(o_w[0], A0),
                                       __fmul_rn(o_w[1], A1)),
                             __fmul_rn(o_w[2], A2));
        float u1 = __fadd_rn(__fadd_rn(__fmul_rn(o_w[3], A0),
                                       __fmul_rn(o_w[4], A3)),
                             __fmul_rn(o_w[5], A4));
        float X0 = __fadd_rn(x0t, u0);
        float X1 = __fadd_rn(dt,  u1);

        float wa = w1_abc[0], wb = w1_abc[1], wc = w1_abc[2];
        float b10 = __fsub_rn(C, 8.0f);
        float b11 = __fsub_rn(C, 9.0f);
        float twoC = __fmul_rn(2.0f, C);
        float b12 = __fsub_rn(twoC, 188.0f);
        float b13 = __fsub_rn(twoC, 189.0f);

        float p01 = __fmaf_rn(X1, 0.0f, __fmul_rn(X0, wa));  // rows 0,1: [a,0]
        float p23 = __fmaf_rn(X1, wc,   __fmul_rn(X0, wb));  // rows 2,3: [b,c]
        float h0 = fmaxf(__fadd_rn(p01, b10), 0.0f);
        float h1 = fmaxf(__fadd_rn(p01, b11), 0.0f);
        float h2 = fmaxf(__fadd_rn(p23, b12), 0.0f);
        float h3 = fmaxf(__fadd_rn(p23, b13), 0.0f);

        float s1 = w2_s[0], s10 = w2_s[1];
        float hw = __fmul_rn(h0, s1);
        hw = __fmaf_rn(h1, -s1,  hw);
        hw = __fmaf_rn(h2, -s10, hw);
        hw = __fmaf_rn(h3,  s10, hw);
        float X1b = __fadd_rn(X1, hw);
        float X0b = __fadd_rn(X0, 0.0f);

        float os0 = __fdiv_rn(1.0f, C);
        float y0 = __fmul_rn(X0b, os0);
        float y1 = __fmul_rn(X1b, eps);

        float* o = out + (size_t)p * V_;
#pragma unroll
        for (int j = 0; j < V_; ++j) {
            float jj = (float)(j * j);
            float e0 = __fsub_rn(C, __fmul_rn(quad, jj));
            o[j] = __fmaf_rn(y1, (float)j, __fmul_rn(y0, e0));
        }
    }
}

// ---------------------------------------------------------------------------
// Inputs (metadata order): input_ids(int32), o_w(6), w1_abc(3), w2_s(2),
// embed_const(1), decode_eps(1), qk_scale(1), rope_offsets(5). Output: f32 BxTxV.
// ---------------------------------------------------------------------------
extern "C" void kernel_launch(void* const* d_in, const int* in_sizes, int n_in,
                              void* d_out, int out_size)
{
    const int*   ids    = (const int*)  d_in[0];
    const float* o_w    = (const float*)d_in[1];
    const float* w1_abc = (const float*)d_in[2];
    const float* w2_s   = (const float*)d_in[3];
    const float* p_C    = (const float*)d_in[4];
    const float* p_eps  = (const float*)d_in[5];
    const float* p_qk   = (const float*)d_in[6];
    const float* offs   = (const float*)d_in[7];
    float* out = (float*)d_out;

    k_prep<<<CAND_BLOCKS + TAB_BLOCKS, 256>>>(ids, offs, p_eps, p_C, p_qk);

    k_fused<<<(B_ * T_) / PAIRS, H_ * PAIRS>>>(ids, o_w, w1_abc, w2_s,
                                               p_C, p_eps, p_qk, offs, out);
}